// round 5
// baseline (speedup 1.0000x reference)
#include <cuda_runtime.h>
#include <cstdint>
#include <cstddef>

#define D 128
#define TILE_ROWS 64
#define GEMM_THREADS 512   // 16 warps: wm = wid&1 (32-row half), wn = wid>>1 (32-col group)

#define NUM_USERS_MAX 100000
#define NUM_ITEMS_MAX 50000
#define NUM_EDGES_MAX 600000

// Scratch (allocation-free rule: device globals)
__device__ float g_U2I[NUM_USERS_MAX * 128];  // user_features @ W_u2i^T  (no bias)
__device__ float g_I2U[NUM_ITEMS_MAX * 128];  // item_features @ W_i2u^T  (no bias)

// CSR scratch
__device__ int g_cnt_i[NUM_ITEMS_MAX];
__device__ int g_cnt_u[NUM_USERS_MAX];
__device__ int g_off_i[NUM_ITEMS_MAX];
__device__ int g_off_u[NUM_USERS_MAX];
__device__ int g_cur_i[NUM_ITEMS_MAX];
__device__ int g_cur_u[NUM_USERS_MAX];
__device__ int g_src_i[NUM_EDGES_MAX];  // for each item-grouped edge: source user
__device__ int g_src_u[NUM_EDGES_MAX];  // for each user-grouped edge: source item

__device__ __forceinline__ float tf32r(float x) {
    float r;
    asm("cvt.rna.tf32.f32 %0, %1;" : "=f"(r) : "f"(x));
    return r;
}

__device__ __forceinline__ void mma_tf32(float* c, const uint32_t* a, uint32_t b0, uint32_t b1) {
    asm volatile(
        "mma.sync.aligned.m16n8k8.row.col.f32.tf32.tf32.f32 "
        "{%0,%1,%2,%3}, {%4,%5,%6,%7}, {%8,%9}, {%0,%1,%2,%3};"
        : "+f"(c[0]), "+f"(c[1]), "+f"(c[2]), "+f"(c[3])
        : "r"(a[0]), "r"(a[1]), "r"(a[2]), "r"(a[3]), "r"(b0), "r"(b1));
}

// smem layout:
//   Wfrag: 16 ksteps x 32 n8-tiles x 32 lanes x float2  = 131072 B at offset 0
//   Xs:    64 rows x 132 floats (pad 4 kills bank conflicts) at 131072
#define XS_OFF_F 32768
#define XS_LD    132
#define SMEM_BYTES (131072 + 64 * XS_LD * 4)

extern __shared__ __align__(16) float smem_f[];

__global__ __launch_bounds__(GEMM_THREADS, 1)
void gemm_mma(const float* __restrict__ X, int nrows,
              const float* __restrict__ Wa, const float* __restrict__ ba,
              const float* __restrict__ Wb,
              float* __restrict__ Yself, float* __restrict__ Ymsg)
{
    float2* Wfrag = (float2*)smem_f;
    float*  Xs    = smem_f + XS_OFF_F;

    const int tid  = threadIdx.x;
    const int lane = tid & 31;
    const int wid  = tid >> 5;
    const int wm   = wid & 1;        // 32-row half of the 64-row tile
    const int wn   = wid >> 1;       // 0..7: 32-col group within 256 outs
    const int g    = lane >> 2;
    const int t    = lane & 3;

    // ---- Build W fragments once (tf32-rounded, fragment-native layout) ----
    for (int i = tid; i < 16 * 32 * 32; i += GEMM_THREADS) {
        const int l  = i & 31;
        const int nt = (i >> 5) & 31;
        const int ks = i >> 10;
        const int o  = nt * 8 + (l >> 2);
        const int k  = ks * 8 + (l & 3);
        const float* Wsrc = (o < 128) ? (Wa + (size_t)o * 128) : (Wb + (size_t)(o - 128) * 128);
        Wfrag[i] = make_float2(tf32r(Wsrc[k]), tf32r(Wsrc[k + 4]));
    }

    float2 bias2[4];
    if (wn < 4) {
        #pragma unroll
        for (int nt = 0; nt < 4; nt++) {
            const int col = wn * 32 + nt * 8 + t * 2;
            bias2[nt] = make_float2(ba[col], ba[col + 1]);
        }
    }

    const int ntiles = (nrows + TILE_ROWS - 1) / TILE_ROWS;

    for (int tile = blockIdx.x; tile < ntiles; tile += gridDim.x) {
        const int row0 = tile * TILE_ROWS;
        __syncthreads();

        for (int i = tid; i < TILE_ROWS * 32; i += GEMM_THREADS) {
            const int r = i >> 5, q = i & 31;
            float4 v = make_float4(0.f, 0.f, 0.f, 0.f);
            if (row0 + r < nrows) {
                v = *(const float4*)&X[(size_t)(row0 + r) * D + q * 4];
                v.x = tf32r(v.x); v.y = tf32r(v.y); v.z = tf32r(v.z); v.w = tf32r(v.w);
            }
            *(float4*)&Xs[r * XS_LD + q * 4] = v;
        }
        __syncthreads();

        float acc[2][4][4];
        #pragma unroll
        for (int mt = 0; mt < 2; mt++)
            #pragma unroll
            for (int nt = 0; nt < 4; nt++)
                #pragma unroll
                for (int j = 0; j < 4; j++) acc[mt][nt][j] = 0.f;

        #pragma unroll 2
        for (int ks = 0; ks < 16; ks++) {
            const int k0 = ks * 8;
            uint32_t a[2][4];
            #pragma unroll
            for (int mt = 0; mt < 2; mt++) {
                const int row = wm * 32 + mt * 16 + g;
                a[mt][0] = __float_as_uint(Xs[row * XS_LD + k0 + t]);
                a[mt][1] = __float_as_uint(Xs[(row + 8) * XS_LD + k0 + t]);
                a[mt][2] = __float_as_uint(Xs[row * XS_LD + k0 + t + 4]);
                a[mt][3] = __float_as_uint(Xs[(row + 8) * XS_LD + k0 + t + 4]);
            }
            #pragma unroll
            for (int nt = 0; nt < 4; nt++) {
                const float2 b = Wfrag[(size_t)(ks * 32 + wn * 4 + nt) * 32 + lane];
                const uint32_t b0 = __float_as_uint(b.x);
                const uint32_t b1 = __float_as_uint(b.y);
                mma_tf32(acc[0][nt], a[0], b0, b1);
                mma_tf32(acc[1][nt], a[1], b0, b1);
            }
        }

        #pragma unroll
        for (int mt = 0; mt < 2; mt++) {
            const int r0 = row0 + wm * 32 + mt * 16 + g;
            const int r1 = r0 + 8;
            #pragma unroll
            for (int nt = 0; nt < 4; nt++) {
                const int colg = wn * 32 + nt * 8 + t * 2;
                if (wn < 4) {
                    if (r0 < nrows)
                        *(float2*)&Yself[(size_t)r0 * D + colg] =
                            make_float2(acc[mt][nt][0] + bias2[nt].x,
                                        acc[mt][nt][1] + bias2[nt].y);
                    if (r1 < nrows)
                        *(float2*)&Yself[(size_t)r1 * D + colg] =
                            make_float2(acc[mt][nt][2] + bias2[nt].x,
                                        acc[mt][nt][3] + bias2[nt].y);
                } else {
                    const int colm = colg - 128;
                    if (r0 < nrows)
                        *(float2*)&Ymsg[(size_t)r0 * D + colm] =
                            make_float2(acc[mt][nt][0], acc[mt][nt][1]);
                    if (r1 < nrows)
                        *(float2*)&Ymsg[(size_t)r1 * D + colm] =
                            make_float2(acc[mt][nt][2], acc[mt][nt][3]);
                }
            }
        }
    }
}

// ============================ CSR build ============================
__global__ void zero_k(int nI, int nU) {
    const int i = blockIdx.x * blockDim.x + threadIdx.x;
    if (i < nI) g_cnt_i[i] = 0;
    if (i < nU) g_cnt_u[i] = 0;
}

__global__ void count_k(const int* __restrict__ eu, const int* __restrict__ ei, int E) {
    const int e = blockIdx.x * blockDim.x + threadIdx.x;
    if (e < E) {
        atomicAdd(&g_cnt_i[__ldg(&ei[e])], 1);
        atomicAdd(&g_cnt_u[__ldg(&eu[e])], 1);
    }
}

// Single-block exclusive scan: off/cur = exclusive prefix of cnt
__global__ void scan_k(const int* __restrict__ cnt, int* __restrict__ off,
                       int* __restrict__ cur, int n)
{
    __shared__ int part[1024];
    const int tid = threadIdx.x;
    const int chunk = (n + 1023) >> 10;
    const int lo = tid * chunk;
    const int hi = min(lo + chunk, n);
    int s = 0;
    for (int i = lo; i < hi; i++) s += cnt[i];
    part[tid] = s;
    __syncthreads();
    // Hillis-Steele inclusive scan over 1024 partials
    #pragma unroll
    for (int d = 1; d < 1024; d <<= 1) {
        int v = (tid >= d) ? part[tid - d] : 0;
        __syncthreads();
        part[tid] += v;
        __syncthreads();
    }
    int run = part[tid] - s;  // exclusive prefix of this thread's chunk
    for (int i = lo; i < hi; i++) {
        off[i] = run;
        cur[i] = run;
        run += cnt[i];
    }
}

__global__ void fill_k(const int* __restrict__ eu, const int* __restrict__ ei, int E) {
    const int e = blockIdx.x * blockDim.x + threadIdx.x;
    if (e < E) {
        const int u  = __ldg(&eu[e]);
        const int it = __ldg(&ei[e]);
        const int p = atomicAdd(&g_cur_i[it], 1);
        g_src_i[p] = u;
        const int q = atomicAdd(&g_cur_u[u], 1);
        g_src_u[q] = it;
    }
}

// ============================ Gather ============================
// One warp per output node: out[node] += sum_j msgs[src[j]] + deg*bias
__global__ void gather_k(const int* __restrict__ off, const int* __restrict__ cnt,
                         const int* __restrict__ src, const float* __restrict__ msgs,
                         const float* __restrict__ bias, float* __restrict__ out, int n)
{
    const int node = (blockIdx.x * blockDim.x + threadIdx.x) >> 5;
    if (node >= n) return;
    const int lane = threadIdx.x & 31;
    const int offc = lane * 4;
    const int base = __ldg(&off[node]);
    const int deg  = __ldg(&cnt[node]);

    float4 acc = make_float4(0.f, 0.f, 0.f, 0.f);
    int j = 0;
    for (; j + 4 <= deg; j += 4) {
        const int s0 = __ldg(&src[base + j]);
        const int s1 = __ldg(&src[base + j + 1]);
        const int s2 = __ldg(&src[base + j + 2]);
        const int s3 = __ldg(&src[base + j + 3]);
        const float4 v0 = *(const float4*)&msgs[(size_t)s0 * D + offc];
        const float4 v1 = *(const float4*)&msgs[(size_t)s1 * D + offc];
        const float4 v2 = *(const float4*)&msgs[(size_t)s2 * D + offc];
        const float4 v3 = *(const float4*)&msgs[(size_t)s3 * D + offc];
        acc.x += (v0.x + v1.x) + (v2.x + v3.x);
        acc.y += (v0.y + v1.y) + (v2.y + v3.y);
        acc.z += (v0.z + v1.z) + (v2.z + v3.z);
        acc.w += (v0.w + v1.w) + (v2.w + v3.w);
    }
    for (; j < deg; j++) {
        const int s = __ldg(&src[base + j]);
        const float4 v = *(const float4*)&msgs[(size_t)s * D + offc];
        acc.x += v.x; acc.y += v.y; acc.z += v.z; acc.w += v.w;
    }

    const float fd = (float)deg;
    const float4 b = *(const float4*)&bias[offc];
    float4* po = (float4*)&out[(size_t)node * D + offc];
    float4 o = *po;
    o.x += acc.x + fd * b.x;
    o.y += acc.y + fd * b.y;
    o.z += acc.z + fd * b.z;
    o.w += acc.w + fd * b.w;
    *po = o;
}

// ============================ Host ============================
extern "C" void kernel_launch(void* const* d_in, const int* in_sizes, int n_in,
                              void* d_out, int out_size)
{
    const float* user_feat = (const float*)d_in[0];
    const float* item_feat = (const float*)d_in[1];
    const int*   edges     = (const int*)d_in[2];
    const float* W_user = (const float*)d_in[3];
    const float* b_user = (const float*)d_in[4];
    const float* W_item = (const float*)d_in[5];
    const float* b_item = (const float*)d_in[6];
    const float* W_u2i  = (const float*)d_in[7];
    const float* b_u2i  = (const float*)d_in[8];
    const float* W_i2u  = (const float*)d_in[9];
    const float* b_i2u  = (const float*)d_in[10];

    const int nU = in_sizes[0] / D;
    const int nI = in_sizes[1] / D;
    const int E  = in_sizes[2] / 2;

    float* user_out = (float*)d_out;
    float* item_out = (float*)d_out + (size_t)nU * D;

    float *u2i_ptr, *i2u_ptr;
    cudaGetSymbolAddress((void**)&u2i_ptr, g_U2I);
    cudaGetSymbolAddress((void**)&i2u_ptr, g_I2U);
    int *cnt_i, *cnt_u, *off_i, *off_u, *src_i, *src_u;
    cudaGetSymbolAddress((void**)&cnt_i, g_cnt_i);
    cudaGetSymbolAddress((void**)&cnt_u, g_cnt_u);
    cudaGetSymbolAddress((void**)&off_i, g_off_i);
    cudaGetSymbolAddress((void**)&off_u, g_off_u);
    cudaGetSymbolAddress((void**)&src_i, g_src_i);
    cudaGetSymbolAddress((void**)&src_u, g_src_u);
    int *cur_i, *cur_u;
    cudaGetSymbolAddress((void**)&cur_i, g_cur_i);
    cudaGetSymbolAddress((void**)&cur_u, g_cur_u);

    // ---- CSR build (independent of GEMMs; stream-ordered) ----
    {
        const int nmax = (nU > nI) ? nU : nI;
        zero_k<<<(nmax + 255) / 256, 256>>>(nI, nU);
        count_k<<<(E + 255) / 256, 256>>>(edges, edges + E, E);
        scan_k<<<1, 1024>>>(cnt_i, off_i, cur_i, nI);
        scan_k<<<1, 1024>>>(cnt_u, off_u, cur_u, nU);
        fill_k<<<(E + 255) / 256, 256>>>(edges, edges + E, E);
    }

    // ---- GEMMs: self-transform into out, message-transform into scratch ----
    cudaFuncSetAttribute(gemm_mma, cudaFuncAttributeMaxDynamicSharedMemorySize, SMEM_BYTES);
    gemm_mma<<<152, GEMM_THREADS, SMEM_BYTES>>>(
        user_feat, nU, W_user, b_user, W_u2i, user_out, u2i_ptr);
    gemm_mma<<<152, GEMM_THREADS, SMEM_BYTES>>>(
        item_feat, nI, W_item, b_item, W_i2u, item_out, i2u_ptr);

    // ---- Gathers: out[node] += sum(messages) + deg*bias ----
    const int wpb = 256 / 32;
    gather_k<<<(nI + wpb - 1) / wpb, 256>>>(off_i, cnt_i, src_i, u2i_ptr, b_u2i, item_out, nI);
    gather_k<<<(nU + wpb - 1) / wpb, 256>>>(off_u, cnt_u, src_u, i2u_ptr, b_i2u, user_out, nU);
}

// round 6
// speedup vs baseline: 1.9362x; 1.9362x over previous
#include <cuda_runtime.h>
#include <cstdint>
#include <cstddef>

#define D 128
#define TILE_ROWS 64
#define GEMM_THREADS 512   // 16 warps: wm = wid&1 (32-row half), wn = wid>>1 (32-col group)

#define NUM_USERS_MAX 100000
#define NUM_ITEMS_MAX 50000
#define NUM_EDGES_MAX 600000

// Scratch (allocation-free rule: device globals)
__device__ float g_U2I[NUM_USERS_MAX * 128];  // user_features @ W_u2i^T  (no bias)
__device__ float g_I2U[NUM_ITEMS_MAX * 128];  // item_features @ W_i2u^T  (no bias)

// CSR scratch
__device__ int g_cnt_i[NUM_ITEMS_MAX];
__device__ int g_cnt_u[NUM_USERS_MAX];
__device__ int g_off_i[NUM_ITEMS_MAX];
__device__ int g_off_u[NUM_USERS_MAX];
__device__ int g_cur_i[NUM_ITEMS_MAX];
__device__ int g_cur_u[NUM_USERS_MAX];
__device__ int g_src_i[NUM_EDGES_MAX];  // for each item-grouped edge: source user
__device__ int g_src_u[NUM_EDGES_MAX];  // for each user-grouped edge: source item
__device__ int g_tot_i;
__device__ int g_tot_u;

__device__ __forceinline__ float tf32r(float x) {
    float r;
    asm("cvt.rna.tf32.f32 %0, %1;" : "=f"(r) : "f"(x));
    return r;
}

__device__ __forceinline__ void mma_tf32(float* c, const uint32_t* a, uint32_t b0, uint32_t b1) {
    asm volatile(
        "mma.sync.aligned.m16n8k8.row.col.f32.tf32.tf32.f32 "
        "{%0,%1,%2,%3}, {%4,%5,%6,%7}, {%8,%9}, {%0,%1,%2,%3};"
        : "+f"(c[0]), "+f"(c[1]), "+f"(c[2]), "+f"(c[3])
        : "r"(a[0]), "r"(a[1]), "r"(a[2]), "r"(a[3]), "r"(b0), "r"(b1));
}

// smem layout:
//   Wfrag: 16 ksteps x 32 n8-tiles x 32 lanes x float2  = 131072 B at offset 0
//   Xs:    64 rows x 132 floats (pad 4 kills bank conflicts) at 131072
#define XS_OFF_F 32768
#define XS_LD    132
#define SMEM_BYTES (131072 + 64 * XS_LD * 4)

extern __shared__ __align__(16) float smem_f[];

__global__ __launch_bounds__(GEMM_THREADS, 1)
void gemm_mma(const float* __restrict__ X, int nrows,
              const float* __restrict__ Wa, const float* __restrict__ ba,
              const float* __restrict__ Wb,
              float* __restrict__ Yself, float* __restrict__ Ymsg)
{
    float2* Wfrag = (float2*)smem_f;
    float*  Xs    = smem_f + XS_OFF_F;

    const int tid  = threadIdx.x;
    const int lane = tid & 31;
    const int wid  = tid >> 5;
    const int wm   = wid & 1;
    const int wn   = wid >> 1;
    const int g    = lane >> 2;
    const int t    = lane & 3;

    for (int i = tid; i < 16 * 32 * 32; i += GEMM_THREADS) {
        const int l  = i & 31;
        const int nt = (i >> 5) & 31;
        const int ks = i >> 10;
        const int o  = nt * 8 + (l >> 2);
        const int k  = ks * 8 + (l & 3);
        const float* Wsrc = (o < 128) ? (Wa + (size_t)o * 128) : (Wb + (size_t)(o - 128) * 128);
        Wfrag[i] = make_float2(tf32r(Wsrc[k]), tf32r(Wsrc[k + 4]));
    }

    float2 bias2[4];
    if (wn < 4) {
        #pragma unroll
        for (int nt = 0; nt < 4; nt++) {
            const int col = wn * 32 + nt * 8 + t * 2;
            bias2[nt] = make_float2(ba[col], ba[col + 1]);
        }
    }

    const int ntiles = (nrows + TILE_ROWS - 1) / TILE_ROWS;

    for (int tile = blockIdx.x; tile < ntiles; tile += gridDim.x) {
        const int row0 = tile * TILE_ROWS;
        __syncthreads();

        for (int i = tid; i < TILE_ROWS * 32; i += GEMM_THREADS) {
            const int r = i >> 5, q = i & 31;
            float4 v = make_float4(0.f, 0.f, 0.f, 0.f);
            if (row0 + r < nrows) {
                v = *(const float4*)&X[(size_t)(row0 + r) * D + q * 4];
                v.x = tf32r(v.x); v.y = tf32r(v.y); v.z = tf32r(v.z); v.w = tf32r(v.w);
            }
            *(float4*)&Xs[r * XS_LD + q * 4] = v;
        }
        __syncthreads();

        float acc[2][4][4];
        #pragma unroll
        for (int mt = 0; mt < 2; mt++)
            #pragma unroll
            for (int nt = 0; nt < 4; nt++)
                #pragma unroll
                for (int j = 0; j < 4; j++) acc[mt][nt][j] = 0.f;

        #pragma unroll 2
        for (int ks = 0; ks < 16; ks++) {
            const int k0 = ks * 8;
            uint32_t a[2][4];
            #pragma unroll
            for (int mt = 0; mt < 2; mt++) {
                const int row = wm * 32 + mt * 16 + g;
                a[mt][0] = __float_as_uint(Xs[row * XS_LD + k0 + t]);
                a[mt][1] = __float_as_uint(Xs[(row + 8) * XS_LD + k0 + t]);
                a[mt][2] = __float_as_uint(Xs[row * XS_LD + k0 + t + 4]);
                a[mt][3] = __float_as_uint(Xs[(row + 8) * XS_LD + k0 + t + 4]);
            }
            #pragma unroll
            for (int nt = 0; nt < 4; nt++) {
                const float2 b = Wfrag[(size_t)(ks * 32 + wn * 4 + nt) * 32 + lane];
                const uint32_t b0 = __float_as_uint(b.x);
                const uint32_t b1 = __float_as_uint(b.y);
                mma_tf32(acc[0][nt], a[0], b0, b1);
                mma_tf32(acc[1][nt], a[1], b0, b1);
            }
        }

        #pragma unroll
        for (int mt = 0; mt < 2; mt++) {
            const int r0 = row0 + wm * 32 + mt * 16 + g;
            const int r1 = r0 + 8;
            #pragma unroll
            for (int nt = 0; nt < 4; nt++) {
                const int colg = wn * 32 + nt * 8 + t * 2;
                if (wn < 4) {
                    if (r0 < nrows)
                        *(float2*)&Yself[(size_t)r0 * D + colg] =
                            make_float2(acc[mt][nt][0] + bias2[nt].x,
                                        acc[mt][nt][1] + bias2[nt].y);
                    if (r1 < nrows)
                        *(float2*)&Yself[(size_t)r1 * D + colg] =
                            make_float2(acc[mt][nt][2] + bias2[nt].x,
                                        acc[mt][nt][3] + bias2[nt].y);
                } else {
                    const int colm = colg - 128;
                    if (r0 < nrows)
                        *(float2*)&Ymsg[(size_t)r0 * D + colm] =
                            make_float2(acc[mt][nt][0], acc[mt][nt][1]);
                    if (r1 < nrows)
                        *(float2*)&Ymsg[(size_t)r1 * D + colm] =
                            make_float2(acc[mt][nt][2], acc[mt][nt][3]);
                }
            }
        }
    }
}

// ============================ CSR build ============================
__global__ void zero_k(int nI, int nU) {
    const int i = blockIdx.x * blockDim.x + threadIdx.x;
    if (i < nI) g_cnt_i[i] = 0;
    if (i < nU) g_cnt_u[i] = 0;
    if (i == 0) { g_tot_i = 0; g_tot_u = 0; }
}

__global__ void count_k(const int* __restrict__ eu, const int* __restrict__ ei, int E) {
    const int e = blockIdx.x * blockDim.x + threadIdx.x;
    if (e < E) {
        atomicAdd(&g_cnt_i[__ldg(&ei[e])], 1);
        atomicAdd(&g_cnt_u[__ldg(&eu[e])], 1);
    }
}

// Chip-wide segment allocator: block-aggregated prefix + ONE atomicAdd per block.
// Segment bases need not be in node order — gather only needs contiguity.
__global__ void alloc_k(const int* __restrict__ cnt, int* __restrict__ off,
                        int* __restrict__ cur, int n, int* __restrict__ total)
{
    __shared__ int wtot[32];
    __shared__ int blk_base;
    const int i = blockIdx.x * blockDim.x + threadIdx.x;
    const int lane = threadIdx.x & 31;
    const int wid = threadIdx.x >> 5;
    const int nw = blockDim.x >> 5;

    const int v = (i < n) ? cnt[i] : 0;

    // warp inclusive prefix
    int p = v;
    #pragma unroll
    for (int d = 1; d < 32; d <<= 1) {
        int t = __shfl_up_sync(0xFFFFFFFFu, p, d);
        if (lane >= d) p += t;
    }
    const int warp_excl = p - v;
    if (lane == 31) wtot[wid] = p;
    __syncthreads();

    if (wid == 0) {
        int wv = (lane < nw) ? wtot[lane] : 0;
        int q = wv;
        #pragma unroll
        for (int d = 1; d < 32; d <<= 1) {
            int t = __shfl_up_sync(0xFFFFFFFFu, q, d);
            if (lane >= d) q += t;
        }
        wtot[lane] = q - wv;            // exclusive warp bases
        if (lane == nw - 1) blk_base = atomicAdd(total, q);  // q = block total
    }
    __syncthreads();

    if (i < n) {
        const int o = blk_base + wtot[wid] + warp_excl;
        off[i] = o;
        cur[i] = o;
    }
}

__global__ void fill_k(const int* __restrict__ eu, const int* __restrict__ ei, int E) {
    const int e = blockIdx.x * blockDim.x + threadIdx.x;
    if (e < E) {
        const int u  = __ldg(&eu[e]);
        const int it = __ldg(&ei[e]);
        const int p = atomicAdd(&g_cur_i[it], 1);
        g_src_i[p] = u;
        const int q = atomicAdd(&g_cur_u[u], 1);
        g_src_u[q] = it;
    }
}

// ============================ Gather ============================
__global__ void gather_k(const int* __restrict__ off, const int* __restrict__ cnt,
                         const int* __restrict__ src, const float* __restrict__ msgs,
                         const float* __restrict__ bias, float* __restrict__ out, int n)
{
    const int node = (blockIdx.x * blockDim.x + threadIdx.x) >> 5;
    if (node >= n) return;
    const int lane = threadIdx.x & 31;
    const int offc = lane * 4;
    const int base = __ldg(&off[node]);
    const int deg  = __ldg(&cnt[node]);

    float4 acc = make_float4(0.f, 0.f, 0.f, 0.f);
    int j = 0;
    for (; j + 4 <= deg; j += 4) {
        const int s0 = __ldg(&src[base + j]);
        const int s1 = __ldg(&src[base + j + 1]);
        const int s2 = __ldg(&src[base + j + 2]);
        const int s3 = __ldg(&src[base + j + 3]);
        const float4 v0 = *(const float4*)&msgs[(size_t)s0 * D + offc];
        const float4 v1 = *(const float4*)&msgs[(size_t)s1 * D + offc];
        const float4 v2 = *(const float4*)&msgs[(size_t)s2 * D + offc];
        const float4 v3 = *(const float4*)&msgs[(size_t)s3 * D + offc];
        acc.x += (v0.x + v1.x) + (v2.x + v3.x);
        acc.y += (v0.y + v1.y) + (v2.y + v3.y);
        acc.z += (v0.z + v1.z) + (v2.z + v3.z);
        acc.w += (v0.w + v1.w) + (v2.w + v3.w);
    }
    for (; j < deg; j++) {
        const int s = __ldg(&src[base + j]);
        const float4 v = *(const float4*)&msgs[(size_t)s * D + offc];
        acc.x += v.x; acc.y += v.y; acc.z += v.z; acc.w += v.w;
    }

    const float fd = (float)deg;
    const float4 b = *(const float4*)&bias[offc];
    float4* po = (float4*)&out[(size_t)node * D + offc];
    float4 o = *po;
    o.x += acc.x + fd * b.x;
    o.y += acc.y + fd * b.y;
    o.z += acc.z + fd * b.z;
    o.w += acc.w + fd * b.w;
    *po = o;
}

// ============================ Host ============================
extern "C" void kernel_launch(void* const* d_in, const int* in_sizes, int n_in,
                              void* d_out, int out_size)
{
    const float* user_feat = (const float*)d_in[0];
    const float* item_feat = (const float*)d_in[1];
    const int*   edges     = (const int*)d_in[2];
    const float* W_user = (const float*)d_in[3];
    const float* b_user = (const float*)d_in[4];
    const float* W_item = (const float*)d_in[5];
    const float* b_item = (const float*)d_in[6];
    const float* W_u2i  = (const float*)d_in[7];
    const float* b_u2i  = (const float*)d_in[8];
    const float* W_i2u  = (const float*)d_in[9];
    const float* b_i2u  = (const float*)d_in[10];

    const int nU = in_sizes[0] / D;
    const int nI = in_sizes[1] / D;
    const int E  = in_sizes[2] / 2;

    float* user_out = (float*)d_out;
    float* item_out = (float*)d_out + (size_t)nU * D;

    float *u2i_ptr, *i2u_ptr;
    cudaGetSymbolAddress((void**)&u2i_ptr, g_U2I);
    cudaGetSymbolAddress((void**)&i2u_ptr, g_I2U);
    int *cnt_i, *cnt_u, *off_i, *off_u, *src_i, *src_u, *cur_i, *cur_u, *tot_i, *tot_u;
    cudaGetSymbolAddress((void**)&cnt_i, g_cnt_i);
    cudaGetSymbolAddress((void**)&cnt_u, g_cnt_u);
    cudaGetSymbolAddress((void**)&off_i, g_off_i);
    cudaGetSymbolAddress((void**)&off_u, g_off_u);
    cudaGetSymbolAddress((void**)&src_i, g_src_i);
    cudaGetSymbolAddress((void**)&src_u, g_src_u);
    cudaGetSymbolAddress((void**)&cur_i, g_cur_i);
    cudaGetSymbolAddress((void**)&cur_u, g_cur_u);
    cudaGetSymbolAddress((void**)&tot_i, g_tot_i);
    cudaGetSymbolAddress((void**)&tot_u, g_tot_u);

    // ---- CSR build ----
    {
        const int nmax = (nU > nI) ? nU : nI;
        zero_k<<<(nmax + 255) / 256, 256>>>(nI, nU);
        count_k<<<(E + 255) / 256, 256>>>(edges, edges + E, E);
        alloc_k<<<(nI + 1023) / 1024, 1024>>>(cnt_i, off_i, cur_i, nI, tot_i);
        alloc_k<<<(nU + 1023) / 1024, 1024>>>(cnt_u, off_u, cur_u, nU, tot_u);
        fill_k<<<(E + 255) / 256, 256>>>(edges, edges + E, E);
    }

    // ---- GEMMs: self-transform into out, message-transform into scratch ----
    cudaFuncSetAttribute(gemm_mma, cudaFuncAttributeMaxDynamicSharedMemorySize, SMEM_BYTES);
    gemm_mma<<<152, GEMM_THREADS, SMEM_BYTES>>>(
        user_feat, nU, W_user, b_user, W_u2i, user_out, u2i_ptr);
    gemm_mma<<<152, GEMM_THREADS, SMEM_BYTES>>>(
        item_feat, nI, W_item, b_item, W_i2u, item_out, i2u_ptr);

    // ---- Gathers: out[node] += sum(messages) + deg*bias ----
    const int wpb = 256 / 32;
    gather_k<<<(nI + wpb - 1) / wpb, 256>>>(off_i, cnt_i, src_i, u2i_ptr, b_u2i, item_out, nI);
    gather_k<<<(nU + wpb - 1) / wpb, 256>>>(off_u, cnt_u, src_u, i2u_ptr, b_i2u, user_out, nU);
}

// round 7
// speedup vs baseline: 2.3530x; 1.2152x over previous
#include <cuda_runtime.h>
#include <cstdint>
#include <cstddef>

#define D 128
#define TILE_ROWS 128
#define GEMM_THREADS 512   // 16 warps: wm = wid&3 (32-row quarter), wn = wid>>2 (64-col group)

#define NUM_USERS_MAX 100000
#define NUM_ITEMS_MAX 50000
#define NUM_EDGES_MAX 600000

// Scratch (allocation-free rule: device globals)
__device__ float g_U2I[NUM_USERS_MAX * 128];
__device__ float g_I2U[NUM_ITEMS_MAX * 128];

// CSR scratch
__device__ int g_cnt_i[NUM_ITEMS_MAX];
__device__ int g_cnt_u[NUM_USERS_MAX];
__device__ int g_off_i[NUM_ITEMS_MAX];
__device__ int g_off_u[NUM_USERS_MAX];
__device__ int g_cur_i[NUM_ITEMS_MAX];
__device__ int g_cur_u[NUM_USERS_MAX];
__device__ int g_src_i[NUM_EDGES_MAX];
__device__ int g_src_u[NUM_EDGES_MAX];
__device__ int g_tot_i;
__device__ int g_tot_u;

__device__ __forceinline__ float tf32r(float x) {
    float r;
    asm("cvt.rna.tf32.f32 %0, %1;" : "=f"(r) : "f"(x));
    return r;
}

__device__ __forceinline__ void mma_tf32(float* c, const uint32_t* a, uint32_t b0, uint32_t b1) {
    asm volatile(
        "mma.sync.aligned.m16n8k8.row.col.f32.tf32.tf32.f32 "
        "{%0,%1,%2,%3}, {%4,%5,%6,%7}, {%8,%9}, {%0,%1,%2,%3};"
        : "+f"(c[0]), "+f"(c[1]), "+f"(c[2]), "+f"(c[3])
        : "r"(a[0]), "r"(a[1]), "r"(a[2]), "r"(a[3]), "r"(b0), "r"(b1));
}

// smem: Wfrag 16ks x 32nt x 32lanes x float2 = 131072 B; Xs 128 x 132 floats
#define XS_OFF_F 32768
#define XS_LD    132
#define SMEM_BYTES (131072 + TILE_ROWS * XS_LD * 4)   // 198656

extern __shared__ __align__(16) float smem_f[];

__global__ __launch_bounds__(GEMM_THREADS, 1)
void gemm_mma(const float* __restrict__ X, int nrows,
              const float* __restrict__ Wa, const float* __restrict__ ba,
              const float* __restrict__ Wb,
              float* __restrict__ Yself, float* __restrict__ Ymsg)
{
    float2* Wfrag = (float2*)smem_f;
    float*  Xs    = smem_f + XS_OFF_F;

    const int tid  = threadIdx.x;
    const int lane = tid & 31;
    const int wid  = tid >> 5;
    const int wm   = wid & 3;        // 32-row quarter of the 128-row tile
    const int wn   = wid >> 2;       // 0..3: 64-col group within 256 outs
    const int g    = lane >> 2;
    const int t    = lane & 3;

    // Build W fragments once (tf32-rounded, fragment-native layout)
    for (int i = tid; i < 16 * 32 * 32; i += GEMM_THREADS) {
        const int l  = i & 31;
        const int nt = (i >> 5) & 31;
        const int ks = i >> 10;
        const int o  = nt * 8 + (l >> 2);
        const int k  = ks * 8 + (l & 3);
        const float* Wsrc = (o < 128) ? (Wa + (size_t)o * 128) : (Wb + (size_t)(o - 128) * 128);
        Wfrag[i] = make_float2(tf32r(Wsrc[k]), tf32r(Wsrc[k + 4]));
    }

    float2 bias2[8];
    if (wn < 2) {
        #pragma unroll
        for (int nt = 0; nt < 8; nt++) {
            const int col = wn * 64 + nt * 8 + t * 2;
            bias2[nt] = make_float2(ba[col], ba[col + 1]);
        }
    }

    const int ntiles = (nrows + TILE_ROWS - 1) / TILE_ROWS;

    for (int tile = blockIdx.x; tile < ntiles; tile += gridDim.x) {
        const int row0 = tile * TILE_ROWS;
        __syncthreads();

        for (int i = tid; i < TILE_ROWS * 32; i += GEMM_THREADS) {
            const int r = i >> 5, q = i & 31;
            float4 v = make_float4(0.f, 0.f, 0.f, 0.f);
            if (row0 + r < nrows) {
                v = *(const float4*)&X[(size_t)(row0 + r) * D + q * 4];
                v.x = tf32r(v.x); v.y = tf32r(v.y); v.z = tf32r(v.z); v.w = tf32r(v.w);
            }
            *(float4*)&Xs[r * XS_LD + q * 4] = v;
        }
        __syncthreads();

        float acc[2][8][4];
        #pragma unroll
        for (int mt = 0; mt < 2; mt++)
            #pragma unroll
            for (int nt = 0; nt < 8; nt++)
                #pragma unroll
                for (int j = 0; j < 4; j++) acc[mt][nt][j] = 0.f;

        #pragma unroll 2
        for (int ks = 0; ks < 16; ks++) {
            const int k0 = ks * 8;
            uint32_t a[2][4];
            #pragma unroll
            for (int mt = 0; mt < 2; mt++) {
                const int row = wm * 32 + mt * 16 + g;
                a[mt][0] = __float_as_uint(Xs[row * XS_LD + k0 + t]);
                a[mt][1] = __float_as_uint(Xs[(row + 8) * XS_LD + k0 + t]);
                a[mt][2] = __float_as_uint(Xs[row * XS_LD + k0 + t + 4]);
                a[mt][3] = __float_as_uint(Xs[(row + 8) * XS_LD + k0 + t + 4]);
            }
            #pragma unroll
            for (int nt = 0; nt < 8; nt++) {
                const float2 b = Wfrag[(size_t)(ks * 32 + wn * 8 + nt) * 32 + lane];
                const uint32_t b0 = __float_as_uint(b.x);
                const uint32_t b1 = __float_as_uint(b.y);
                mma_tf32(acc[0][nt], a[0], b0, b1);
                mma_tf32(acc[1][nt], a[1], b0, b1);
            }
        }

        #pragma unroll
        for (int mt = 0; mt < 2; mt++) {
            const int r0 = row0 + wm * 32 + mt * 16 + g;
            const int r1 = r0 + 8;
            #pragma unroll
            for (int nt = 0; nt < 8; nt++) {
                const int colg = wn * 64 + nt * 8 + t * 2;
                if (wn < 2) {
                    if (r0 < nrows)
                        *(float2*)&Yself[(size_t)r0 * D + colg] =
                            make_float2(acc[mt][nt][0] + bias2[nt].x,
                                        acc[mt][nt][1] + bias2[nt].y);
                    if (r1 < nrows)
                        *(float2*)&Yself[(size_t)r1 * D + colg] =
                            make_float2(acc[mt][nt][2] + bias2[nt].x,
                                        acc[mt][nt][3] + bias2[nt].y);
                } else {
                    const int colm = colg - 128;
                    if (r0 < nrows)
                        *(float2*)&Ymsg[(size_t)r0 * D + colm] =
                            make_float2(acc[mt][nt][0], acc[mt][nt][1]);
                    if (r1 < nrows)
                        *(float2*)&Ymsg[(size_t)r1 * D + colm] =
                            make_float2(acc[mt][nt][2], acc[mt][nt][3]);
                }
            }
        }
    }
}

// ============================ CSR build ============================
__global__ void zero_k(int nI, int nU) {
    const int i = blockIdx.x * blockDim.x + threadIdx.x;
    if (i < nI) g_cnt_i[i] = 0;
    if (i < nU) g_cnt_u[i] = 0;
    if (i == 0) { g_tot_i = 0; g_tot_u = 0; }
}

__global__ void count_k(const int* __restrict__ eu, const int* __restrict__ ei, int E) {
    const int e = blockIdx.x * blockDim.x + threadIdx.x;
    if (e < E) {
        atomicAdd(&g_cnt_i[__ldg(&ei[e])], 1);
        atomicAdd(&g_cnt_u[__ldg(&eu[e])], 1);
    }
}

// Chip-wide segment allocator: block prefix + ONE atomicAdd per block.
__global__ void alloc_k(const int* __restrict__ cnt, int* __restrict__ off,
                        int* __restrict__ cur, int n, int* __restrict__ total)
{
    __shared__ int wtot[32];
    __shared__ int blk_base;
    const int i = blockIdx.x * blockDim.x + threadIdx.x;
    const int lane = threadIdx.x & 31;
    const int wid = threadIdx.x >> 5;
    const int nw = blockDim.x >> 5;

    const int v = (i < n) ? cnt[i] : 0;

    int p = v;
    #pragma unroll
    for (int d = 1; d < 32; d <<= 1) {
        int t = __shfl_up_sync(0xFFFFFFFFu, p, d);
        if (lane >= d) p += t;
    }
    const int warp_excl = p - v;
    if (lane == 31) wtot[wid] = p;
    __syncthreads();

    if (wid == 0) {
        int wv = (lane < nw) ? wtot[lane] : 0;
        int q = wv;
        #pragma unroll
        for (int d = 1; d < 32; d <<= 1) {
            int t = __shfl_up_sync(0xFFFFFFFFu, q, d);
            if (lane >= d) q += t;
        }
        wtot[lane] = q - wv;
        if (lane == nw - 1) blk_base = atomicAdd(total, q);
    }
    __syncthreads();

    if (i < n) {
        const int o = blk_base + wtot[wid] + warp_excl;
        off[i] = o;
        cur[i] = o;
    }
}

__global__ void fill_k(const int* __restrict__ eu, const int* __restrict__ ei, int E) {
    const int e = blockIdx.x * blockDim.x + threadIdx.x;
    if (e < E) {
        const int u  = __ldg(&eu[e]);
        const int it = __ldg(&ei[e]);
        const int p = atomicAdd(&g_cur_i[it], 1);
        g_src_i[p] = u;
        const int q = atomicAdd(&g_cur_u[u], 1);
        g_src_u[q] = it;
    }
}

// ============================ Gather ============================
__global__ void gather_k(const int* __restrict__ off, const int* __restrict__ cnt,
                         const int* __restrict__ src, const float* __restrict__ msgs,
                         const float* __restrict__ bias, float* __restrict__ out, int n)
{
    const int node = (blockIdx.x * blockDim.x + threadIdx.x) >> 5;
    if (node >= n) return;
    const int lane = threadIdx.x & 31;
    const int offc = lane * 4;
    const int base = __ldg(&off[node]);
    const int deg  = __ldg(&cnt[node]);

    float4 acc = make_float4(0.f, 0.f, 0.f, 0.f);
    int j = 0;
    for (; j + 4 <= deg; j += 4) {
        const int s0 = __ldg(&src[base + j]);
        const int s1 = __ldg(&src[base + j + 1]);
        const int s2 = __ldg(&src[base + j + 2]);
        const int s3 = __ldg(&src[base + j + 3]);
        const float4 v0 = *(const float4*)&msgs[(size_t)s0 * D + offc];
        const float4 v1 = *(const float4*)&msgs[(size_t)s1 * D + offc];
        const float4 v2 = *(const float4*)&msgs[(size_t)s2 * D + offc];
        const float4 v3 = *(const float4*)&msgs[(size_t)s3 * D + offc];
        acc.x += (v0.x + v1.x) + (v2.x + v3.x);
        acc.y += (v0.y + v1.y) + (v2.y + v3.y);
        acc.z += (v0.z + v1.z) + (v2.z + v3.z);
        acc.w += (v0.w + v1.w) + (v2.w + v3.w);
    }
    for (; j < deg; j++) {
        const int s = __ldg(&src[base + j]);
        const float4 v = *(const float4*)&msgs[(size_t)s * D + offc];
        acc.x += v.x; acc.y += v.y; acc.z += v.z; acc.w += v.w;
    }

    const float fd = (float)deg;
    const float4 b = *(const float4*)&bias[offc];
    float4* po = (float4*)&out[(size_t)node * D + offc];
    float4 o = *po;
    o.x += acc.x + fd * b.x;
    o.y += acc.y + fd * b.y;
    o.z += acc.z + fd * b.z;
    o.w += acc.w + fd * b.w;
    *po = o;
}

// ============================ Host ============================
struct Ctx {
    cudaStream_t s1, s2;
    cudaEvent_t evFork, evCSR, evI, evU, evS2;
    Ctx() {
        cudaStreamCreateWithFlags(&s1, cudaStreamNonBlocking);
        cudaStreamCreateWithFlags(&s2, cudaStreamNonBlocking);
        cudaEventCreateWithFlags(&evFork, cudaEventDisableTiming);
        cudaEventCreateWithFlags(&evCSR,  cudaEventDisableTiming);
        cudaEventCreateWithFlags(&evI,    cudaEventDisableTiming);
        cudaEventCreateWithFlags(&evU,    cudaEventDisableTiming);
        cudaEventCreateWithFlags(&evS2,   cudaEventDisableTiming);
    }
};

extern "C" void kernel_launch(void* const* d_in, const int* in_sizes, int n_in,
                              void* d_out, int out_size)
{
    const float* user_feat = (const float*)d_in[0];
    const float* item_feat = (const float*)d_in[1];
    const int*   edges     = (const int*)d_in[2];
    const float* W_user = (const float*)d_in[3];
    const float* b_user = (const float*)d_in[4];
    const float* W_item = (const float*)d_in[5];
    const float* b_item = (const float*)d_in[6];
    const float* W_u2i  = (const float*)d_in[7];
    const float* b_u2i  = (const float*)d_in[8];
    const float* W_i2u  = (const float*)d_in[9];
    const float* b_i2u  = (const float*)d_in[10];

    const int nU = in_sizes[0] / D;
    const int nI = in_sizes[1] / D;
    const int E  = in_sizes[2] / 2;

    float* user_out = (float*)d_out;
    float* item_out = (float*)d_out + (size_t)nU * D;

    float *u2i_ptr, *i2u_ptr;
    cudaGetSymbolAddress((void**)&u2i_ptr, g_U2I);
    cudaGetSymbolAddress((void**)&i2u_ptr, g_I2U);
    int *cnt_i, *cnt_u, *off_i, *off_u, *src_i, *src_u, *cur_i, *cur_u, *tot_i, *tot_u;
    cudaGetSymbolAddress((void**)&cnt_i, g_cnt_i);
    cudaGetSymbolAddress((void**)&cnt_u, g_cnt_u);
    cudaGetSymbolAddress((void**)&off_i, g_off_i);
    cudaGetSymbolAddress((void**)&off_u, g_off_u);
    cudaGetSymbolAddress((void**)&src_i, g_src_i);
    cudaGetSymbolAddress((void**)&src_u, g_src_u);
    cudaGetSymbolAddress((void**)&cur_i, g_cur_i);
    cudaGetSymbolAddress((void**)&cur_u, g_cur_u);
    cudaGetSymbolAddress((void**)&tot_i, g_tot_i);
    cudaGetSymbolAddress((void**)&tot_u, g_tot_u);

    cudaFuncSetAttribute(gemm_mma, cudaFuncAttributeMaxDynamicSharedMemorySize, SMEM_BYTES);

    // One-time host-side objects (identical captured device work on every call)
    static Ctx ctx;
    const cudaStream_t L = 0;      // captured legacy stream

    // ---- fork ----
    cudaEventRecord(ctx.evFork, L);
    cudaStreamWaitEvent(ctx.s1, ctx.evFork, 0);
    cudaStreamWaitEvent(ctx.s2, ctx.evFork, 0);

    // ---- s1: CSR build ----
    {
        const int nmax = (nU > nI) ? nU : nI;
        zero_k<<<(nmax + 255) / 256, 256, 0, ctx.s1>>>(nI, nU);
        count_k<<<(E + 255) / 256, 256, 0, ctx.s1>>>(edges, edges + E, E);
        alloc_k<<<(nI + 1023) / 1024, 1024, 0, ctx.s1>>>(cnt_i, off_i, cur_i, nI, tot_i);
        alloc_k<<<(nU + 1023) / 1024, 1024, 0, ctx.s1>>>(cnt_u, off_u, cur_u, nU, tot_u);
        fill_k<<<(E + 255) / 256, 256, 0, ctx.s1>>>(edges, edges + E, E);
        cudaEventRecord(ctx.evCSR, ctx.s1);
    }

    // ---- s2: item GEMM ----
    gemm_mma<<<152, GEMM_THREADS, SMEM_BYTES, ctx.s2>>>(
        item_feat, nI, W_item, b_item, W_i2u, item_out, i2u_ptr);
    cudaEventRecord(ctx.evI, ctx.s2);

    // ---- L: user GEMM (concurrent with s1, s2) ----
    gemm_mma<<<152, GEMM_THREADS, SMEM_BYTES, L>>>(
        user_feat, nU, W_user, b_user, W_u2i, user_out, u2i_ptr);
    cudaEventRecord(ctx.evU, L);

    // ---- gathers: each needs CSR + BOTH gemms (RMW of out halves) ----
    const int wpb = 256 / 32;
    cudaStreamWaitEvent(L, ctx.evCSR, 0);
    cudaStreamWaitEvent(L, ctx.evI, 0);
    gather_k<<<(nI + wpb - 1) / wpb, 256, 0, L>>>(
        off_i, cnt_i, src_i, u2i_ptr, b_u2i, item_out, nI);

    cudaStreamWaitEvent(ctx.s2, ctx.evCSR, 0);
    cudaStreamWaitEvent(ctx.s2, ctx.evU, 0);
    gather_k<<<(nU + wpb - 1) / wpb, 256, 0, ctx.s2>>>(
        off_u, cnt_u, src_u, i2u_ptr, b_i2u, user_out, nU);
    cudaEventRecord(ctx.evS2, ctx.s2);

    // ---- join ----
    cudaStreamWaitEvent(L, ctx.evS2, 0);
}

// round 8
// speedup vs baseline: 2.7959x; 1.1883x over previous
#include <cuda_runtime.h>
#include <cuda_fp16.h>
#include <cstdint>
#include <cstddef>

#define D 128
#define TILE_ROWS 128
#define GEMM_THREADS 512   // 16 warps: wm = wid&3 (32-row quarter), wn = wid>>2 (64-col group)

#define NUM_USERS_MAX 100000
#define NUM_ITEMS_MAX 50000
#define NUM_EDGES_MAX 600000

// Scratch (allocation-free rule: device globals). Messages stored fp16.
__device__ __half g_U2I[NUM_USERS_MAX * 128];
__device__ __half g_I2U[NUM_ITEMS_MAX * 128];

// CSR scratch
__device__ int g_cnt_i[NUM_ITEMS_MAX];
__device__ int g_cnt_u[NUM_USERS_MAX];
__device__ int g_off_i[NUM_ITEMS_MAX];
__device__ int g_off_u[NUM_USERS_MAX];
__device__ int g_cur_i[NUM_ITEMS_MAX];
__device__ int g_cur_u[NUM_USERS_MAX];
__device__ int g_src_i[NUM_EDGES_MAX];
__device__ int g_src_u[NUM_EDGES_MAX];
__device__ int g_tot_i;
__device__ int g_tot_u;

__device__ __forceinline__ float tf32r(float x) {
    float r;
    asm("cvt.rna.tf32.f32 %0, %1;" : "=f"(r) : "f"(x));
    return r;
}

__device__ __forceinline__ void mma_tf32(float* c, const uint32_t* a, uint32_t b0, uint32_t b1) {
    asm volatile(
        "mma.sync.aligned.m16n8k8.row.col.f32.tf32.tf32.f32 "
        "{%0,%1,%2,%3}, {%4,%5,%6,%7}, {%8,%9}, {%0,%1,%2,%3};"
        : "+f"(c[0]), "+f"(c[1]), "+f"(c[2]), "+f"(c[3])
        : "r"(a[0]), "r"(a[1]), "r"(a[2]), "r"(a[3]), "r"(b0), "r"(b1));
}

// smem: Wfrag 16ks x 32nt x 32lanes x float2 = 131072 B; Xs 128 x 132 floats
#define XS_OFF_F 32768
#define XS_LD    132
#define SMEM_BYTES (131072 + TILE_ROWS * XS_LD * 4)   // 198656

extern __shared__ __align__(16) float smem_f[];

// Unified persistent GEMM: blocks [0, split) process the user matrices,
// blocks [split, gridDim) the item matrices. One launch -> no grid serialization.
__global__ __launch_bounds__(GEMM_THREADS, 1)
void gemm_mma(const float* __restrict__ Xu, int nu,
              const float* __restrict__ Wau, const float* __restrict__ bau,
              const float* __restrict__ Wbu,
              float* __restrict__ Yu, __half* __restrict__ Mu,
              const float* __restrict__ Xi, int ni,
              const float* __restrict__ Wai, const float* __restrict__ bai,
              const float* __restrict__ Wbi,
              float* __restrict__ Yi, __half* __restrict__ Mi,
              int split)
{
    float2* Wfrag = (float2*)smem_f;
    float*  Xs    = smem_f + XS_OFF_F;

    const int tid  = threadIdx.x;
    const int lane = tid & 31;
    const int wid  = tid >> 5;
    const int wm   = wid & 3;        // 32-row quarter of the 128-row tile
    const int wn   = wid >> 2;       // 0..3: 64-col group within 256 outs
    const int g    = lane >> 2;
    const int t    = lane & 3;

    // Per-block work selection
    const float *X, *Wa, *ba, *Wb;
    float* Yself;
    __half* Ymsg;
    int nrows, bidx, nblk;
    if (blockIdx.x < split) {
        X = Xu; Wa = Wau; ba = bau; Wb = Wbu; Yself = Yu; Ymsg = Mu;
        nrows = nu; bidx = blockIdx.x; nblk = split;
    } else {
        X = Xi; Wa = Wai; ba = bai; Wb = Wbi; Yself = Yi; Ymsg = Mi;
        nrows = ni; bidx = blockIdx.x - split; nblk = gridDim.x - split;
    }

    // Build W fragments once (tf32-rounded, fragment-native layout)
    for (int i = tid; i < 16 * 32 * 32; i += GEMM_THREADS) {
        const int l  = i & 31;
        const int nt = (i >> 5) & 31;
        const int ks = i >> 10;
        const int o  = nt * 8 + (l >> 2);
        const int k  = ks * 8 + (l & 3);
        const float* Wsrc = (o < 128) ? (Wa + (size_t)o * 128) : (Wb + (size_t)(o - 128) * 128);
        Wfrag[i] = make_float2(tf32r(Wsrc[k]), tf32r(Wsrc[k + 4]));
    }

    float2 bias2[8];
    if (wn < 2) {
        #pragma unroll
        for (int nt = 0; nt < 8; nt++) {
            const int col = wn * 64 + nt * 8 + t * 2;
            bias2[nt] = make_float2(ba[col], ba[col + 1]);
        }
    }

    const int ntiles = (nrows + TILE_ROWS - 1) / TILE_ROWS;

    for (int tile = bidx; tile < ntiles; tile += nblk) {
        const int row0 = tile * TILE_ROWS;
        __syncthreads();

        for (int i = tid; i < TILE_ROWS * 32; i += GEMM_THREADS) {
            const int r = i >> 5, q = i & 31;
            float4 v = make_float4(0.f, 0.f, 0.f, 0.f);
            if (row0 + r < nrows) {
                v = *(const float4*)&X[(size_t)(row0 + r) * D + q * 4];
                v.x = tf32r(v.x); v.y = tf32r(v.y); v.z = tf32r(v.z); v.w = tf32r(v.w);
            }
            *(float4*)&Xs[r * XS_LD + q * 4] = v;
        }
        __syncthreads();

        float acc[2][8][4];
        #pragma unroll
        for (int mt = 0; mt < 2; mt++)
            #pragma unroll
            for (int nt = 0; nt < 8; nt++)
                #pragma unroll
                for (int j = 0; j < 4; j++) acc[mt][nt][j] = 0.f;

        #pragma unroll 2
        for (int ks = 0; ks < 16; ks++) {
            const int k0 = ks * 8;
            uint32_t a[2][4];
            #pragma unroll
            for (int mt = 0; mt < 2; mt++) {
                const int row = wm * 32 + mt * 16 + g;
                a[mt][0] = __float_as_uint(Xs[row * XS_LD + k0 + t]);
                a[mt][1] = __float_as_uint(Xs[(row + 8) * XS_LD + k0 + t]);
                a[mt][2] = __float_as_uint(Xs[row * XS_LD + k0 + t + 4]);
                a[mt][3] = __float_as_uint(Xs[(row + 8) * XS_LD + k0 + t + 4]);
            }
            #pragma unroll
            for (int nt = 0; nt < 8; nt++) {
                const float2 b = Wfrag[(size_t)(ks * 32 + wn * 8 + nt) * 32 + lane];
                const uint32_t b0 = __float_as_uint(b.x);
                const uint32_t b1 = __float_as_uint(b.y);
                mma_tf32(acc[0][nt], a[0], b0, b1);
                mma_tf32(acc[1][nt], a[1], b0, b1);
            }
        }

        #pragma unroll
        for (int mt = 0; mt < 2; mt++) {
            const int r0 = row0 + wm * 32 + mt * 16 + g;
            const int r1 = r0 + 8;
            #pragma unroll
            for (int nt = 0; nt < 8; nt++) {
                const int colg = wn * 64 + nt * 8 + t * 2;
                if (wn < 2) {
                    if (r0 < nrows)
                        *(float2*)&Yself[(size_t)r0 * D + colg] =
                            make_float2(acc[mt][nt][0] + bias2[nt].x,
                                        acc[mt][nt][1] + bias2[nt].y);
                    if (r1 < nrows)
                        *(float2*)&Yself[(size_t)r1 * D + colg] =
                            make_float2(acc[mt][nt][2] + bias2[nt].x,
                                        acc[mt][nt][3] + bias2[nt].y);
                } else {
                    const int colm = colg - 128;
                    if (r0 < nrows)
                        *(__half2*)&Ymsg[(size_t)r0 * D + colm] =
                            __floats2half2_rn(acc[mt][nt][0], acc[mt][nt][1]);
                    if (r1 < nrows)
                        *(__half2*)&Ymsg[(size_t)r1 * D + colm] =
                            __floats2half2_rn(acc[mt][nt][2], acc[mt][nt][3]);
                }
            }
        }
    }
}

// ============================ CSR build ============================
__global__ void zero_k(int nI, int nU) {
    const int i = blockIdx.x * blockDim.x + threadIdx.x;
    if (i < nI) g_cnt_i[i] = 0;
    if (i < nU) g_cnt_u[i] = 0;
    if (i == 0) { g_tot_i = 0; g_tot_u = 0; }
}

__global__ void count_k(const int* __restrict__ eu, const int* __restrict__ ei, int E) {
    const int e = blockIdx.x * blockDim.x + threadIdx.x;
    if (e < E) {
        atomicAdd(&g_cnt_i[__ldg(&ei[e])], 1);
        atomicAdd(&g_cnt_u[__ldg(&eu[e])], 1);
    }
}

// Chip-wide segment allocator: block prefix + ONE atomicAdd per block.
__global__ void alloc_k(const int* __restrict__ cnt, int* __restrict__ off,
                        int* __restrict__ cur, int n, int* __restrict__ total)
{
    __shared__ int wtot[32];
    __shared__ int blk_base;
    const int i = blockIdx.x * blockDim.x + threadIdx.x;
    const int lane = threadIdx.x & 31;
    const int wid = threadIdx.x >> 5;
    const int nw = blockDim.x >> 5;

    const int v = (i < n) ? cnt[i] : 0;

    int p = v;
    #pragma unroll
    for (int d = 1; d < 32; d <<= 1) {
        int t = __shfl_up_sync(0xFFFFFFFFu, p, d);
        if (lane >= d) p += t;
    }
    const int warp_excl = p - v;
    if (lane == 31) wtot[wid] = p;
    __syncthreads();

    if (wid == 0) {
        int wv = (lane < nw) ? wtot[lane] : 0;
        int q = wv;
        #pragma unroll
        for (int d = 1; d < 32; d <<= 1) {
            int t = __shfl_up_sync(0xFFFFFFFFu, q, d);
            if (lane >= d) q += t;
        }
        wtot[lane] = q - wv;
        if (lane == nw - 1) blk_base = atomicAdd(total, q);
    }
    __syncthreads();

    if (i < n) {
        const int o = blk_base + wtot[wid] + warp_excl;
        off[i] = o;
        cur[i] = o;
    }
}

__global__ void fill_k(const int* __restrict__ eu, const int* __restrict__ ei, int E) {
    const int e = blockIdx.x * blockDim.x + threadIdx.x;
    if (e < E) {
        const int u  = __ldg(&eu[e]);
        const int it = __ldg(&ei[e]);
        const int p = atomicAdd(&g_cur_i[it], 1);
        g_src_i[p] = u;
        const int q = atomicAdd(&g_cur_u[u], 1);
        g_src_u[q] = it;
    }
}

// ============================ Gather (fp16 messages) ============================
__device__ __forceinline__ void acc_half4(float4& acc, uint2 raw) {
    const __half2 h0 = *(__half2*)&raw.x;
    const __half2 h1 = *(__half2*)&raw.y;
    const float2 f0 = __half22float2(h0);
    const float2 f1 = __half22float2(h1);
    acc.x += f0.x; acc.y += f0.y; acc.z += f1.x; acc.w += f1.y;
}

__global__ void gather_k(const int* __restrict__ off, const int* __restrict__ cnt,
                         const int* __restrict__ src, const __half* __restrict__ msgs,
                         const float* __restrict__ bias, float* __restrict__ out, int n)
{
    const int node = (blockIdx.x * blockDim.x + threadIdx.x) >> 5;
    if (node >= n) return;
    const int lane = threadIdx.x & 31;
    const int offc = lane * 4;
    const int base = __ldg(&off[node]);
    const int deg  = __ldg(&cnt[node]);

    float4 acc = make_float4(0.f, 0.f, 0.f, 0.f);
    int j = 0;
    for (; j + 4 <= deg; j += 4) {
        const int s0 = __ldg(&src[base + j]);
        const int s1 = __ldg(&src[base + j + 1]);
        const int s2 = __ldg(&src[base + j + 2]);
        const int s3 = __ldg(&src[base + j + 3]);
        const uint2 r0 = *(const uint2*)&msgs[(size_t)s0 * D + offc];
        const uint2 r1 = *(const uint2*)&msgs[(size_t)s1 * D + offc];
        const uint2 r2 = *(const uint2*)&msgs[(size_t)s2 * D + offc];
        const uint2 r3 = *(const uint2*)&msgs[(size_t)s3 * D + offc];
        acc_half4(acc, r0); acc_half4(acc, r1);
        acc_half4(acc, r2); acc_half4(acc, r3);
    }
    for (; j < deg; j++) {
        const int s = __ldg(&src[base + j]);
        acc_half4(acc, *(const uint2*)&msgs[(size_t)s * D + offc]);
    }

    const float fd = (float)deg;
    const float4 b = *(const float4*)&bias[offc];
    float4* po = (float4*)&out[(size_t)node * D + offc];
    float4 o = *po;
    o.x += acc.x + fd * b.x;
    o.y += acc.y + fd * b.y;
    o.z += acc.z + fd * b.z;
    o.w += acc.w + fd * b.w;
    *po = o;
}

// ============================ Host ============================
struct Ctx {
    cudaStream_t s1, s2;
    cudaEvent_t evFork, evCSR, evG, evS2;
    Ctx() {
        cudaStreamCreateWithFlags(&s1, cudaStreamNonBlocking);
        cudaStreamCreateWithFlags(&s2, cudaStreamNonBlocking);
        cudaEventCreateWithFlags(&evFork, cudaEventDisableTiming);
        cudaEventCreateWithFlags(&evCSR,  cudaEventDisableTiming);
        cudaEventCreateWithFlags(&evG,    cudaEventDisableTiming);
        cudaEventCreateWithFlags(&evS2,   cudaEventDisableTiming);
    }
};

extern "C" void kernel_launch(void* const* d_in, const int* in_sizes, int n_in,
                              void* d_out, int out_size)
{
    const float* user_feat = (const float*)d_in[0];
    const float* item_feat = (const float*)d_in[1];
    const int*   edges     = (const int*)d_in[2];
    const float* W_user = (const float*)d_in[3];
    const float* b_user = (const float*)d_in[4];
    const float* W_item = (const float*)d_in[5];
    const float* b_item = (const float*)d_in[6];
    const float* W_u2i  = (const float*)d_in[7];
    const float* b_u2i  = (const float*)d_in[8];
    const float* W_i2u  = (const float*)d_in[9];
    const float* b_i2u  = (const float*)d_in[10];

    const int nU = in_sizes[0] / D;
    const int nI = in_sizes[1] / D;
    const int E  = in_sizes[2] / 2;

    float* user_out = (float*)d_out;
    float* item_out = (float*)d_out + (size_t)nU * D;

    __half *u2i_ptr, *i2u_ptr;
    cudaGetSymbolAddress((void**)&u2i_ptr, g_U2I);
    cudaGetSymbolAddress((void**)&i2u_ptr, g_I2U);
    int *cnt_i, *cnt_u, *off_i, *off_u, *src_i, *src_u, *cur_i, *cur_u, *tot_i, *tot_u;
    cudaGetSymbolAddress((void**)&cnt_i, g_cnt_i);
    cudaGetSymbolAddress((void**)&cnt_u, g_cnt_u);
    cudaGetSymbolAddress((void**)&off_i, g_off_i);
    cudaGetSymbolAddress((void**)&off_u, g_off_u);
    cudaGetSymbolAddress((void**)&src_i, g_src_i);
    cudaGetSymbolAddress((void**)&src_u, g_src_u);
    cudaGetSymbolAddress((void**)&cur_i, g_cur_i);
    cudaGetSymbolAddress((void**)&cur_u, g_cur_u);
    cudaGetSymbolAddress((void**)&tot_i, g_tot_i);
    cudaGetSymbolAddress((void**)&tot_u, g_tot_u);

    cudaFuncSetAttribute(gemm_mma, cudaFuncAttributeMaxDynamicSharedMemorySize, SMEM_BYTES);

    static Ctx ctx;
    const cudaStream_t L = 0;      // captured legacy stream

    // ---- fork: CSR build runs concurrently with the GEMM ----
    cudaEventRecord(ctx.evFork, L);
    cudaStreamWaitEvent(ctx.s1, ctx.evFork, 0);
    {
        const int nmax = (nU > nI) ? nU : nI;
        zero_k<<<(nmax + 255) / 256, 256, 0, ctx.s1>>>(nI, nU);
        count_k<<<(E + 255) / 256, 256, 0, ctx.s1>>>(edges, edges + E, E);
        alloc_k<<<(nI + 1023) / 1024, 1024, 0, ctx.s1>>>(cnt_i, off_i, cur_i, nI, tot_i);
        alloc_k<<<(nU + 1023) / 1024, 1024, 0, ctx.s1>>>(cnt_u, off_u, cur_u, nU, tot_u);
        fill_k<<<(E + 255) / 256, 256, 0, ctx.s1>>>(edges, edges + E, E);
        cudaEventRecord(ctx.evCSR, ctx.s1);
    }

    // ---- L: single unified GEMM launch (user + item blocks side by side) ----
    int split = (int)((152LL * nU) / (nU + nI));
    if (split < 1) split = 1;
    if (split > 151) split = 151;
    gemm_mma<<<152, GEMM_THREADS, SMEM_BYTES, L>>>(
        user_feat, nU, W_user, b_user, W_u2i, user_out, u2i_ptr,
        item_feat, nI, W_item, b_item, W_i2u, item_out, i2u_ptr,
        split);
    cudaEventRecord(ctx.evG, L);

    // ---- gathers (concurrent on two streams; need GEMM + CSR) ----
    const int wpb = 256 / 32;
    cudaStreamWaitEvent(L, ctx.evCSR, 0);
    gather_k<<<(nI + wpb - 1) / wpb, 256, 0, L>>>(
        off_i, cnt_i, src_i, u2i_ptr, b_u2i, item_out, nI);

    cudaStreamWaitEvent(ctx.s2, ctx.evG, 0);
    cudaStreamWaitEvent(ctx.s2, ctx.evCSR, 0);
    gather_k<<<(nU + wpb - 1) / wpb, 256, 0, ctx.s2>>>(
        off_u, cnt_u, src_u, i2u_ptr, b_i2u, user_out, nU);
    cudaEventRecord(ctx.evS2, ctx.s2);

    // ---- join ----
    cudaStreamWaitEvent(L, ctx.evS2, 0);
}